// round 13
// baseline (speedup 1.0000x reference)
#include <cuda_runtime.h>
#include <cstdint>

// CostVolume2D: out[n, dy*9+dx, h, w] = mean_c f1[n,c,h,w] * f2pad[n,c,h+dy,w+dx]
// N=8, C=128, H=96, W=224, D=4 -> 81 channels. fp32.
//
// R13 = R8 (best: 134.2us, proven schedule kept intact) with one change:
// f1 is PRIVATE per thread (no intra-block sharing), so it skips SMEM entirely.
// Each thread LDG.128s its own 4 f1 pixels per channel, issued BEFORE the
// cp.async wait so L2 latency overlaps the pipeline wait. Removes 4/10 LDGSTS,
// 4/16 LDS.128 per thread/chunk and 16 KB smem. s2 path identical to R8
// (+ ulonglong2 pair loads, the isolated ALU win from R11).

#define N_ 8
#define C_ 128
#define H_ 96
#define W_ 224

constexpr int TH = 16;
constexpr int TW = 32;
constexpr int DG = 3;          // dy per block (9 split across gridDim.z)
constexpr int CCH = 4;         // channels per pipeline stage
constexpr int NCHUNK = C_ / CCH;   // 32
constexpr int THREADS = 128;   // blockDim = (8,16)
constexpr int RW  = TW + 8;    // 40 padded row
constexpr int S2R = TH + 2;    // 18 rows
constexpr int F2_F4 = CCH * S2R * (RW / 4);  // 720

__device__ __forceinline__ void cp_async16(uint32_t dst, const void* src, bool pred) {
    int sz = pred ? 16 : 0;
    asm volatile("cp.async.cg.shared.global [%0], [%1], 16, %2;\n"
                 :: "r"(dst), "l"(src), "r"(sz));
}
__device__ __forceinline__ void cp_commit() {
    asm volatile("cp.async.commit_group;\n" ::);
}
__device__ __forceinline__ void cp_wait1() {
    asm volatile("cp.async.wait_group 1;\n" ::);
}

__device__ __forceinline__ uint64_t pk2(float lo, float hi) {
    uint64_t r; asm("mov.b64 %0, {%1, %2};" : "=l"(r) : "f"(lo), "f"(hi)); return r;
}
__device__ __forceinline__ void fma2(uint64_t& acc, uint64_t a, uint64_t b) {
    asm("fma.rn.f32x2 %0, %1, %2, %0;" : "+l"(acc) : "l"(a), "l"(b));
}
__device__ __forceinline__ void upk(uint64_t v, float& lo, float& hi) {
    asm("mov.b64 {%0, %1}, %2;" : "=f"(lo), "=f"(hi) : "l"(v));
}

__global__ __launch_bounds__(THREADS, 3)
void costvol_kernel(const float* __restrict__ f1,
                    const float* __restrict__ f2,
                    float* __restrict__ out)
{
    __shared__ __align__(16) float s2[2][CCH][S2R][RW];  // 23 KB (f2 only)

    const int tx  = threadIdx.x;           // 0..7
    const int ty  = threadIdx.y;           // 0..15
    const int tid = ty * 8 + tx;

    const int tile_x = blockIdx.x * TW;
    const int tile_y = blockIdx.y * TH;
    const int g      = blockIdx.z % 3;
    const int n      = blockIdx.z / 3;     // n-major z for L2 locality
    const int dy0    = 3 * g;

    const float* f1n = f1 + (size_t)n * C_ * H_ * W_;
    const float* f2n = f2 + (size_t)n * C_ * H_ * W_;

    // this thread's private f1 pointer (4 pixels), advanced by channel
    const float* f1t = f1n + (size_t)(tile_y + ty) * W_ + tile_x + tx * 4;

    const uint32_t s2b = (uint32_t)__cvta_generic_to_shared(&s2[0][0][0][0]);

    // ---- precompute chunk-invariant f2 staging descriptors (6 f4/thread) ----
    int  off2[6];
    int  sm2[6];
    bool pr2[6];
    bool act2[6];
#pragma unroll
    for (int i = 0; i < 6; i++) {
        int idx = tid + THREADS * i;
        act2[i] = (idx < F2_F4);
        int id  = act2[i] ? idx : 0;
        int c   = id / (S2R * RW / 4);
        int rem = id - c * (S2R * RW / 4);
        int r   = rem / (RW / 4);
        int q   = rem - r * (RW / 4);
        int gy  = tile_y + dy0 - 4 + r;
        bool valid = ((unsigned)gy < (unsigned)H_)
                   && !(q == 0 && tile_x == 0)
                   && !(q == 9 && tile_x + TW + 4 > W_);
        int gyc = valid ? gy : 0;
        off2[i] = (c * H_ + gyc) * W_ + tile_x - 4 + q * 4;
        if (q == 0 && tile_x == 0) off2[i] += 4;  // keep ptr in-bounds (sz=0)
        sm2[i]  = ((c * S2R + r) * RW + q * 4) * 4;
        pr2[i]  = valid;
    }

    // packed accumulators: pp=0 -> pixels (0,1), pp=1 -> (2,3)
    uint64_t acc0[DG][9], acc1[DG][9];
#pragma unroll
    for (int d = 0; d < DG; d++)
#pragma unroll
        for (int x = 0; x < 9; x++) { acc0[d][x] = 0ull; acc1[d][x] = 0ull; }

    auto stage = [&](int buf, int cb) {
        const float* f2c = f2n + (size_t)cb * CCH * H_ * W_;
        uint32_t d2 = s2b + (uint32_t)(buf * (CCH * S2R * RW * 4));
#pragma unroll
        for (int i = 0; i < 6; i++) {
            if (act2[i])
                cp_async16(d2 + (uint32_t)sm2[i], f2c + off2[i], pr2[i]);
        }
    };

    // ---- pipeline prologue ----
    stage(0, 0); cp_commit();
    stage(1, 1); cp_commit();

    for (int cb = 0; cb < NCHUNK; cb++) {
        // f1 loads for this chunk: independent of cp.async/barrier, issue first
        // so L2 latency overlaps the pipeline wait.
        ulonglong2 av[CCH];
#pragma unroll
        for (int c = 0; c < CCH; c++)
            av[c] = *reinterpret_cast<const ulonglong2*>(
                f1t + (size_t)(cb * CCH + c) * H_ * W_);

        cp_wait1();
        __syncthreads();

        const int buf = cb & 1;
#pragma unroll
        for (int c = 0; c < CCH; c++) {
            const uint64_t a01 = av[c].x;
            const uint64_t a23 = av[c].y;
#pragma unroll
            for (int dyi = 0; dyi < DG; dyi++) {
                const float* row = &s2[buf][c][ty + dyi][tx * 4];
                ulonglong2 e01 = *reinterpret_cast<const ulonglong2*>(row);
                ulonglong2 e23 = *reinterpret_cast<const ulonglong2*>(row + 4);
                ulonglong2 e45 = *reinterpret_cast<const ulonglong2*>(row + 8);
                uint64_t pe[6] = {e01.x, e01.y, e23.x, e23.y, e45.x, e45.y};

                // even-dx fma2s (native pairs, no packs)
#pragma unroll
                for (int dx = 0; dx < 9; dx += 2) {
                    fma2(acc0[dyi][dx], a01, pe[dx >> 1]);
                    fma2(acc1[dyi][dx], a23, pe[(dx >> 1) + 1]);
                }

                // odd pairs: 5 packs from register halves
                float r0, r1, r2, r3, r4, r5, r6, r7, r8, r9, r10, r11;
                upk(pe[0], r0, r1);  upk(pe[1], r2, r3);
                upk(pe[2], r4, r5);  upk(pe[3], r6, r7);
                upk(pe[4], r8, r9);  upk(pe[5], r10, r11);
                uint64_t po[5];
                po[0] = pk2(r1, r2);  po[1] = pk2(r3, r4);
                po[2] = pk2(r5, r6);  po[3] = pk2(r7, r8);
                po[4] = pk2(r9, r10);

#pragma unroll
                for (int dx = 1; dx < 9; dx += 2) {
                    fma2(acc0[dyi][dx], a01, po[dx >> 1]);
                    fma2(acc1[dyi][dx], a23, po[(dx >> 1) + 1]);
                }
            }
        }

        __syncthreads();       // all warps done reading buf before restaging
        if (cb + 2 < NCHUNK) stage(buf, cb + 2);
        cp_commit();           // uniform group accounting
    }

    // ---- epilogue ----
    const float inv = 1.0f / (float)C_;
    float* outn = out + (size_t)n * 81 * H_ * W_;
    const int y = tile_y + ty;
    const int x = tile_x + tx * 4;
#pragma unroll
    for (int dyi = 0; dyi < DG; dyi++)
#pragma unroll
        for (int dx = 0; dx < 9; dx++) {
            int k = (dy0 + dyi) * 9 + dx;
            float v0, v1, v2, v3;
            upk(acc0[dyi][dx], v0, v1);
            upk(acc1[dyi][dx], v2, v3);
            float4 v = make_float4(v0 * inv, v1 * inv, v2 * inv, v3 * inv);
            *reinterpret_cast<float4*>(outn + ((size_t)k * H_ + y) * W_ + x) = v;
        }
}

extern "C" void kernel_launch(void* const* d_in, const int* in_sizes, int n_in,
                              void* d_out, int out_size)
{
    const float* f1 = (const float*)d_in[0];
    const float* f2 = (const float*)d_in[1];
    float* out = (float*)d_out;

    dim3 block(8, 16);
    dim3 grid(W_ / TW, H_ / TH, N_ * 3);   // 7 x 6 x 24 = 1008
    costvol_kernel<<<grid, block>>>(f1, f2, out);
}

// round 14
// speedup vs baseline: 1.7544x; 1.7544x over previous
#include <cuda_runtime.h>
#include <cstdint>

// CostVolume2D: out[n, dy*9+dx, h, w] = mean_c f1[n,c,h,w] * f2pad[n,c,h+dy,w+dx]
// N=8, C=128, H=96, W=224, D=4 -> 81 channels. fp32.
//
// R14 = R8 (best: 134.2us) VERBATIM except ONE isolated change:
// inner-body smem loads use ulonglong2 so the a-pair and the 6 even r-pairs
// are born as aligned 64-bit register pairs (no pack MOVs); only the 5 odd
// pairs are packed. Staging, sync schedule, FMA order: identical to R8.

#define N_ 8
#define C_ 128
#define H_ 96
#define W_ 224

constexpr int TH = 16;
constexpr int TW = 32;
constexpr int DG = 3;         // dy offsets per block (9 split across gridDim.z)
constexpr int CCH = 4;        // channels per pipeline stage
constexpr int NCHUNK = C_ / CCH;   // 32
constexpr int THREADS = 128;  // blockDim = (8,16)
constexpr int RW  = TW + 8;   // 40 padded row
constexpr int S2R = TH + 2;   // 18 rows
constexpr int F2_F4 = CCH * S2R * (RW / 4);  // 720 float4 per stage
constexpr int F1_F4 = CCH * TH * (TW / 4);   // 512 float4 per stage

__device__ __forceinline__ void cp_async16(uint32_t dst, const void* src, bool pred) {
    int sz = pred ? 16 : 0;
    asm volatile("cp.async.cg.shared.global [%0], [%1], 16, %2;\n"
                 :: "r"(dst), "l"(src), "r"(sz));
}
__device__ __forceinline__ void cp_commit() {
    asm volatile("cp.async.commit_group;\n" ::);
}
__device__ __forceinline__ void cp_wait1() {
    asm volatile("cp.async.wait_group 1;\n" ::);
}

__device__ __forceinline__ uint64_t pk2(float lo, float hi) {
    uint64_t r; asm("mov.b64 %0, {%1, %2};" : "=l"(r) : "f"(lo), "f"(hi)); return r;
}
__device__ __forceinline__ void fma2(uint64_t& acc, uint64_t a, uint64_t b) {
    asm("fma.rn.f32x2 %0, %1, %2, %0;" : "+l"(acc) : "l"(a), "l"(b));
}
__device__ __forceinline__ void upk(uint64_t v, float& lo, float& hi) {
    asm("mov.b64 {%0, %1}, %2;" : "=f"(lo), "=f"(hi) : "l"(v));
}

__global__ __launch_bounds__(THREADS, 3)
void costvol_kernel(const float* __restrict__ f1,
                    const float* __restrict__ f2,
                    float* __restrict__ out)
{
    __shared__ __align__(16) float s1[2][CCH][TH][TW];   // 16 KB
    __shared__ __align__(16) float s2[2][CCH][S2R][RW];  // 23 KB

    const int tx  = threadIdx.x;          // 0..7
    const int ty  = threadIdx.y;          // 0..15
    const int tid = ty * 8 + tx;

    const int tile_x = blockIdx.x * TW;
    const int tile_y = blockIdx.y * TH;
    const int g      = blockIdx.z % 3;
    const int n      = blockIdx.z / 3;    // n-major z for L2 locality
    const int dy0    = 3 * g;

    const float* f1n = f1 + (size_t)n * C_ * H_ * W_;
    const float* f2n = f2 + (size_t)n * C_ * H_ * W_;

    const uint32_t s1b = (uint32_t)__cvta_generic_to_shared(&s1[0][0][0][0]);
    const uint32_t s2b = (uint32_t)__cvta_generic_to_shared(&s2[0][0][0][0]);

    // ---- chunk-invariant f2 staging descriptors (6 f4/thread) ----
    int  off2[6];
    int  sm2[6];
    bool pr2[6];
    bool act2[6];
#pragma unroll
    for (int i = 0; i < 6; i++) {
        int idx = tid + THREADS * i;
        act2[i] = (idx < F2_F4);
        int id  = act2[i] ? idx : 0;
        int c   = id / (S2R * RW / 4);
        int rem = id - c * (S2R * RW / 4);
        int r   = rem / (RW / 4);
        int q   = rem - r * (RW / 4);
        int gy  = tile_y + dy0 - 4 + r;
        bool valid = ((unsigned)gy < (unsigned)H_)
                   && !(q == 0 && tile_x == 0)
                   && !(q == (RW / 4 - 1) && tile_x + TW + 4 > W_);
        int gyc = valid ? gy : 0;
        off2[i] = (c * H_ + gyc) * W_ + tile_x - 4 + q * 4;
        if (q == 0 && tile_x == 0) off2[i] += 4;  // keep ptr in-bounds (unread, sz=0)
        sm2[i]  = ((c * S2R + r) * RW + q * 4) * 4;
        pr2[i]  = valid;
    }

    // packed accumulators: pp=0 -> pixels (0,1), pp=1 -> (2,3)
    uint64_t acc0[DG][9], acc1[DG][9];
#pragma unroll
    for (int d = 0; d < DG; d++)
#pragma unroll
        for (int x = 0; x < 9; x++) { acc0[d][x] = 0ull; acc1[d][x] = 0ull; }

    auto stage = [&](int buf, int cb) {
        const float* f1c = f1n + (size_t)cb * CCH * H_ * W_;
        const float* f2c = f2n + (size_t)cb * CCH * H_ * W_;
        uint32_t d1 = s1b + (uint32_t)buf * (CCH * TH * TW * 4);
        uint32_t d2 = s2b + (uint32_t)buf * (CCH * S2R * RW * 4);
#pragma unroll
        for (int i = 0; i < F1_F4 / THREADS; i++) {
            int idx = tid + THREADS * i;
            int c   = idx >> 7;
            int rem = idx & 127;
            int r   = rem >> 3;
            int q   = rem & 7;
            cp_async16(d1 + (uint32_t)(((c * TH + r) * TW + q * 4) * 4),
                       f1c + ((size_t)c * H_ + tile_y + r) * W_ + tile_x + q * 4,
                       true);
        }
#pragma unroll
        for (int i = 0; i < 6; i++) {
            if (act2[i])
                cp_async16(d2 + (uint32_t)sm2[i], f2c + off2[i], pr2[i]);
        }
    };

    // ---- pipeline prologue ----
    stage(0, 0); cp_commit();
    stage(1, 1); cp_commit();

    for (int cb = 0; cb < NCHUNK; cb++) {
        cp_wait1();
        __syncthreads();

        const int buf = cb & 1;
#pragma unroll
        for (int c = 0; c < CCH; c++) {
            uint64_t a01, a23;
            {
                ulonglong2 av = *reinterpret_cast<const ulonglong2*>(
                    &s1[buf][c][ty][tx * 4]);
                a01 = av.x; a23 = av.y;
            }
#pragma unroll
            for (int dyi = 0; dyi < DG; dyi++) {
                const float* row = &s2[buf][c][ty + dyi][tx * 4];
                ulonglong2 e01 = *reinterpret_cast<const ulonglong2*>(row);
                ulonglong2 e23 = *reinterpret_cast<const ulonglong2*>(row + 4);
                ulonglong2 e45 = *reinterpret_cast<const ulonglong2*>(row + 8);
                uint64_t pe[6] = {e01.x, e01.y, e23.x, e23.y, e45.x, e45.y};

                // even-dx fma2s (operands are native pairs, no packs)
#pragma unroll
                for (int dx = 0; dx < 9; dx += 2) {
                    fma2(acc0[dyi][dx], a01, pe[dx >> 1]);
                    fma2(acc1[dyi][dx], a23, pe[(dx >> 1) + 1]);
                }

                // odd pairs: 5 packs from register halves
                float r0, r1, r2, r3, r4, r5, r6, r7, r8, r9, r10, r11;
                upk(pe[0], r0, r1);  upk(pe[1], r2, r3);
                upk(pe[2], r4, r5);  upk(pe[3], r6, r7);
                upk(pe[4], r8, r9);  upk(pe[5], r10, r11);
                uint64_t po[5];
                po[0] = pk2(r1, r2);  po[1] = pk2(r3, r4);
                po[2] = pk2(r5, r6);  po[3] = pk2(r7, r8);
                po[4] = pk2(r9, r10);

#pragma unroll
                for (int dx = 1; dx < 9; dx += 2) {
                    fma2(acc0[dyi][dx], a01, po[dx >> 1]);
                    fma2(acc1[dyi][dx], a23, po[(dx >> 1) + 1]);
                }
            }
        }

        __syncthreads();
        if (cb + 2 < NCHUNK) stage(buf, cb + 2);
        cp_commit();
    }

    // ---- epilogue ----
    const float inv = 1.0f / (float)C_;
    float* outn = out + (size_t)n * 81 * H_ * W_;
    const int y = tile_y + ty;
    const int x = tile_x + tx * 4;
#pragma unroll
    for (int dyi = 0; dyi < DG; dyi++)
#pragma unroll
        for (int dx = 0; dx < 9; dx++) {
            int k = (dy0 + dyi) * 9 + dx;
            float v0, v1, v2, v3;
            upk(acc0[dyi][dx], v0, v1);
            upk(acc1[dyi][dx], v2, v3);
            float4 v = make_float4(v0 * inv, v1 * inv, v2 * inv, v3 * inv);
            *reinterpret_cast<float4*>(outn + ((size_t)k * H_ + y) * W_ + x) = v;
        }
}

extern "C" void kernel_launch(void* const* d_in, const int* in_sizes, int n_in,
                              void* d_out, int out_size)
{
    const float* f1 = (const float*)d_in[0];
    const float* f2 = (const float*)d_in[1];
    float* out = (float*)d_out;

    dim3 block(8, 16);
    dim3 grid(W_ / TW, H_ / TH, N_ * 3);   // 7 x 6 x 24
    costvol_kernel<<<grid, block>>>(f1, f2, out);
}

// round 15
// speedup vs baseline: 1.7572x; 1.0016x over previous
#include <cuda_runtime.h>
#include <cstdint>

// CostVolume2D: out[n, dy*9+dx, h, w] = mean_c f1[n,c,h,w] * f2pad[n,c,h+dy,w+dx]
// N=8, C=128, H=96, W=224, D=4 -> 81 channels. fp32.
//
// R15 = R8 (best: 134.2us) with sharing scope changed from BLOCK to WARP:
// each of the 4 warps owns a private smem partition (its 4 f1 rows + its 6
// padded f2 rows, incl. 2-row halo duplicated vs neighbors) and runs its own
// depth-2 cp.async pipeline. All __syncthreads become __syncwarp (~23cyc,
// no cross-warp drain coupling). Compute body is R8-verbatim (float4 + pk2).
// Cost: +33% s2 staging traffic (L2 has headroom). smem 46.7KB -> 3 CTAs/SM.

#define N_ 8
#define C_ 128
#define H_ 96
#define W_ 224

constexpr int TH = 16;        // tile height (4 rows per warp)
constexpr int TW = 32;        // tile width
constexpr int DG = 3;         // dy offsets per block (9 split across gridDim.z)
constexpr int CCH = 4;        // channels per pipeline stage
constexpr int NCHUNK = C_ / CCH;   // 32
constexpr int THREADS = 128;  // 4 warps; warp w owns rows [4w, 4w+3]
constexpr int RW  = TW + 8;   // 40 padded row
constexpr int WR1 = 4;        // f1 rows per warp
constexpr int WR2 = 6;        // padded f2 rows per warp (4 + DG-1 halo... 4+2)
constexpr int S1W = CCH * WR1 * TW;   // 512 floats per warp per stage
constexpr int S2W = CCH * WR2 * RW;   // 960 floats per warp per stage
constexpr int F2_F4W = S2W / 4;       // 240 float4 per warp stage
constexpr int F1_F4W = S1W / 4;       // 128 float4 per warp stage

__device__ __forceinline__ void cp_async16(uint32_t dst, const void* src, bool pred) {
    int sz = pred ? 16 : 0;
    asm volatile("cp.async.cg.shared.global [%0], [%1], 16, %2;\n"
                 :: "r"(dst), "l"(src), "r"(sz));
}
__device__ __forceinline__ void cp_commit() {
    asm volatile("cp.async.commit_group;\n" ::);
}
__device__ __forceinline__ void cp_wait1() {
    asm volatile("cp.async.wait_group 1;\n" ::);
}

__device__ __forceinline__ uint64_t pk2(float lo, float hi) {
    uint64_t r; asm("mov.b64 %0, {%1, %2};" : "=l"(r) : "f"(lo), "f"(hi)); return r;
}
__device__ __forceinline__ void fma2(uint64_t& acc, uint64_t a, uint64_t b) {
    asm("fma.rn.f32x2 %0, %1, %2, %0;" : "+l"(acc) : "l"(a), "l"(b));
}
__device__ __forceinline__ void upk(uint64_t v, float& lo, float& hi) {
    asm("mov.b64 {%0, %1}, %2;" : "=f"(lo), "=f"(hi) : "l"(v));
}

__global__ __launch_bounds__(THREADS, 3)
void costvol_kernel(const float* __restrict__ f1,
                    const float* __restrict__ f2,
                    float* __restrict__ out)
{
    // warp-private partitions: [warp][stage][...]
    __shared__ __align__(16) float s1[4][2][S1W];   // 16 KB
    __shared__ __align__(16) float s2[4][2][S2W];   // 30.7 KB

    const int tid  = threadIdx.y * 8 + threadIdx.x;
    const int warp = tid >> 5;             // 0..3
    const int lane = tid & 31;
    const int tx   = lane & 7;             // 0..7  (x: 4 pixels each)
    const int tyl  = lane >> 3;            // 0..3  (row within warp)
    const int ty   = warp * 4 + tyl;       // 0..15 (row within tile)

    const int tile_x = blockIdx.x * TW;
    const int tile_y = blockIdx.y * TH;
    const int g      = blockIdx.z % 3;
    const int n      = blockIdx.z / 3;     // n-major z for L2 locality
    const int dy0    = 3 * g;

    const float* f1n = f1 + (size_t)n * C_ * H_ * W_;
    const float* f2n = f2 + (size_t)n * C_ * H_ * W_;

    const uint32_t s1b = (uint32_t)__cvta_generic_to_shared(&s1[warp][0][0]);
    const uint32_t s2b = (uint32_t)__cvta_generic_to_shared(&s2[warp][0][0]);

    // ---- chunk-invariant f2 staging descriptors: 8 f4/lane (240 total) ----
    // warp stages padded rows gy = tile_y + dy0 - 4 + 4*warp + rr, rr in [0,6)
    int  off2[8];
    int  sm2[8];
    bool pr2[8];
    bool act2[8];
#pragma unroll
    for (int i = 0; i < 8; i++) {
        int idx = lane + 32 * i;
        act2[i] = (idx < F2_F4W);
        int id  = act2[i] ? idx : 0;
        int c   = id / (WR2 * RW / 4);            // /60
        int rem = id - c * (WR2 * RW / 4);
        int rr  = rem / (RW / 4);                 // /10, 0..5
        int q   = rem - rr * (RW / 4);            // 0..9
        int gy  = tile_y + dy0 - 4 + 4 * warp + rr;
        bool valid = ((unsigned)gy < (unsigned)H_)
                   && !(q == 0 && tile_x == 0)
                   && !(q == 9 && tile_x + TW + 4 > W_);
        int gyc = valid ? gy : 0;
        off2[i] = (c * H_ + gyc) * W_ + tile_x - 4 + q * 4;
        if (q == 0 && tile_x == 0) off2[i] += 4;  // keep ptr in-bounds (sz=0)
        sm2[i]  = ((c * WR2 + rr) * RW + q * 4) * 4;
        pr2[i]  = valid;
    }

    // packed accumulators: pp=0 -> pixels (0,1), pp=1 -> (2,3)
    uint64_t acc0[DG][9], acc1[DG][9];
#pragma unroll
    for (int d = 0; d < DG; d++)
#pragma unroll
        for (int x = 0; x < 9; x++) { acc0[d][x] = 0ull; acc1[d][x] = 0ull; }

    // ---- warp-private staging ----
    auto stage = [&](int buf, int cb) {
        const float* f1c = f1n + (size_t)cb * CCH * H_ * W_;
        const float* f2c = f2n + (size_t)cb * CCH * H_ * W_;
        uint32_t d1 = s1b + (uint32_t)(buf * (S1W * 4));
        uint32_t d2 = s2b + (uint32_t)(buf * (S2W * 4));
        // f1: 128 f4 / 32 lanes = 4 each; rows tile_y + 4*warp + r
#pragma unroll
        for (int i = 0; i < F1_F4W / 32; i++) {
            int idx = lane + 32 * i;
            int c   = idx >> 5;            // /32 f4 per channel (4 rows x 8)
            int rem = idx & 31;
            int r   = rem >> 3;            // 0..3
            int q   = rem & 7;
            cp_async16(d1 + (uint32_t)(((c * WR1 + r) * TW + q * 4) * 4),
                       f1c + ((size_t)c * H_ + tile_y + 4 * warp + r) * W_
                           + tile_x + q * 4,
                       true);
        }
#pragma unroll
        for (int i = 0; i < 8; i++) {
            if (act2[i])
                cp_async16(d2 + (uint32_t)sm2[i], f2c + off2[i], pr2[i]);
        }
    };

    // ---- pipeline prologue (depth 2, per warp) ----
    stage(0, 0); cp_commit();
    stage(1, 1); cp_commit();

    for (int cb = 0; cb < NCHUNK; cb++) {
        cp_wait1();
        __syncwarp();          // lanes' async writes visible warp-wide

        const int buf = cb & 1;
        const float* s1base = &s1[warp][buf][0];
        const float* s2base = &s2[warp][buf][0];

#pragma unroll
        for (int c = 0; c < CCH; c++) {
            uint64_t a01, a23;
            {
                float4 av = *reinterpret_cast<const float4*>(
                    s1base + (size_t)(c * WR1 + tyl) * TW + tx * 4);
                a01 = pk2(av.x, av.y);
                a23 = pk2(av.z, av.w);
            }
#pragma unroll
            for (int dyi = 0; dyi < DG; dyi++) {
                const float* row = s2base + (size_t)(c * WR2 + tyl + dyi) * RW + tx * 4;
                float4 b0 = *reinterpret_cast<const float4*>(row);
                float4 b1 = *reinterpret_cast<const float4*>(row + 4);
                float4 b2 = *reinterpret_cast<const float4*>(row + 8);
                // even pairs (natural register pairs from the float4 loads)
                uint64_t pe0 = pk2(b0.x, b0.y);
                uint64_t pe1 = pk2(b0.z, b0.w);
                uint64_t pe2 = pk2(b1.x, b1.y);
                uint64_t pe3 = pk2(b1.z, b1.w);
                uint64_t pe4 = pk2(b2.x, b2.y);
                uint64_t pe5 = pk2(b2.z, b2.w);
                // odd pairs (cross-pair packs)
                uint64_t po0 = pk2(b0.y, b0.z);
                uint64_t po1 = pk2(b0.w, b1.x);
                uint64_t po2 = pk2(b1.y, b1.z);
                uint64_t po3 = pk2(b1.w, b2.x);
                uint64_t po4 = pk2(b2.y, b2.z);

                uint64_t pr[11] = {pe0, po0, pe1, po1, pe2, po2,
                                   pe3, po3, pe4, po4, pe5};
#pragma unroll
                for (int dx = 0; dx < 9; dx++) {
                    fma2(acc0[dyi][dx], a01, pr[dx]);
                    fma2(acc1[dyi][dx], a23, pr[dx + 2]);
                }
            }
        }

        __syncwarp();          // all lanes done reading buf before restaging
        if (cb + 2 < NCHUNK) stage(buf, cb + 2);
        cp_commit();           // uniform group accounting
    }

    // ---- epilogue ----
    const float inv = 1.0f / (float)C_;
    float* outn = out + (size_t)n * 81 * H_ * W_;
    const int y = tile_y + ty;
    const int x = tile_x + tx * 4;
#pragma unroll
    for (int dyi = 0; dyi < DG; dyi++)
#pragma unroll
        for (int dx = 0; dx < 9; dx++) {
            int k = (dy0 + dyi) * 9 + dx;
            float v0, v1, v2, v3;
            upk(acc0[dyi][dx], v0, v1);
            upk(acc1[dyi][dx], v2, v3);
            float4 v = make_float4(v0 * inv, v1 * inv, v2 * inv, v3 * inv);
            *reinterpret_cast<float4*>(outn + ((size_t)k * H_ + y) * W_ + x) = v;
        }
}

extern "C" void kernel_launch(void* const* d_in, const int* in_sizes, int n_in,
                              void* d_out, int out_size)
{
    const float* f1 = (const float*)d_in[0];
    const float* f2 = (const float*)d_in[1];
    float* out = (float*)d_out;

    dim3 block(8, 16);
    dim3 grid(W_ / TW, H_ / TH, N_ * 3);   // 7 x 6 x 24 = 1008
    costvol_kernel<<<grid, block>>>(f1, f2, out);
}

// round 16
// speedup vs baseline: 1.8387x; 1.0464x over previous
#include <cuda_runtime.h>
#include <cstdint>

// CostVolume2D: out[n, dy*9+dx, h, w] = mean_c f1[n,c,h,w] * f2pad[n,c,h+dy,w+dx]
// N=8, C=128, H=96, W=224, D=4 -> 81 channels. fp32.
//
// R16 = R8 (best: 134.2us) with ONE change: tile height 16 -> 8 (64 threads,
// 6 CTAs/SM, same 12 warps/SM). Fixes wave quantization: grid 1008 -> 2016
// uniform blocks; slots run 5x~23.5us instead of 3x~44.8us (=134.4, the exact
// measured time). Per-CTA code, schedule, and body are R8-verbatim.

#define N_ 8
#define C_ 128
#define H_ 96
#define W_ 224

constexpr int TH = 8;         // tile height (was 16)
constexpr int TW = 32;        // tile width
constexpr int DG = 3;         // dy offsets per block (9 split across gridDim.z)
constexpr int CCH = 4;        // channels per pipeline stage
constexpr int NCHUNK = C_ / CCH;   // 32
constexpr int THREADS = 64;   // blockDim = (8,8)
constexpr int RW  = TW + 8;   // 40 padded row
constexpr int S2R = TH + 2;   // 10 rows
constexpr int F2_F4 = CCH * S2R * (RW / 4);  // 400 float4 per stage
constexpr int F1_F4 = CCH * TH * (TW / 4);   // 256 float4 per stage
constexpr int ND2 = (F2_F4 + THREADS - 1) / THREADS;  // 7 descriptor slots

__device__ __forceinline__ void cp_async16(uint32_t dst, const void* src, bool pred) {
    int sz = pred ? 16 : 0;
    asm volatile("cp.async.cg.shared.global [%0], [%1], 16, %2;\n"
                 :: "r"(dst), "l"(src), "r"(sz));
}
__device__ __forceinline__ void cp_commit() {
    asm volatile("cp.async.commit_group;\n" ::);
}
__device__ __forceinline__ void cp_wait1() {
    asm volatile("cp.async.wait_group 1;\n" ::);
}

__device__ __forceinline__ uint64_t pk2(float lo, float hi) {
    uint64_t r; asm("mov.b64 %0, {%1, %2};" : "=l"(r) : "f"(lo), "f"(hi)); return r;
}
__device__ __forceinline__ void fma2(uint64_t& acc, uint64_t a, uint64_t b) {
    asm("fma.rn.f32x2 %0, %1, %2, %0;" : "+l"(acc) : "l"(a), "l"(b));
}
__device__ __forceinline__ void upk(uint64_t v, float& lo, float& hi) {
    asm("mov.b64 {%0, %1}, %2;" : "=f"(lo), "=f"(hi) : "l"(v));
}

__global__ __launch_bounds__(THREADS, 6)
void costvol_kernel(const float* __restrict__ f1,
                    const float* __restrict__ f2,
                    float* __restrict__ out)
{
    __shared__ __align__(16) float s1[2][CCH][TH][TW];   // 8 KB
    __shared__ __align__(16) float s2[2][CCH][S2R][RW];  // 12.8 KB

    const int tx  = threadIdx.x;          // 0..7
    const int ty  = threadIdx.y;          // 0..7
    const int tid = ty * 8 + tx;          // 0..63

    const int tile_x = blockIdx.x * TW;
    const int tile_y = blockIdx.y * TH;
    const int g      = blockIdx.z % 3;
    const int n      = blockIdx.z / 3;    // n-major z for L2 locality
    const int dy0    = 3 * g;

    const float* f1n = f1 + (size_t)n * C_ * H_ * W_;
    const float* f2n = f2 + (size_t)n * C_ * H_ * W_;

    const uint32_t s1b = (uint32_t)__cvta_generic_to_shared(&s1[0][0][0][0]);
    const uint32_t s2b = (uint32_t)__cvta_generic_to_shared(&s2[0][0][0][0]);

    // ---- chunk-invariant f2 staging descriptors (ND2 f4/thread) ----
    int  off2[ND2];
    int  sm2[ND2];
    bool pr2[ND2];
    bool act2[ND2];
#pragma unroll
    for (int i = 0; i < ND2; i++) {
        int idx = tid + THREADS * i;
        act2[i] = (idx < F2_F4);
        int id  = act2[i] ? idx : 0;
        int c   = id / (S2R * RW / 4);            // /100
        int rem = id - c * (S2R * RW / 4);
        int r   = rem / (RW / 4);                 // /10, 0..9
        int q   = rem - r * (RW / 4);             // 0..9
        int gy  = tile_y + dy0 - 4 + r;
        bool valid = ((unsigned)gy < (unsigned)H_)
                   && !(q == 0 && tile_x == 0)
                   && !(q == (RW / 4 - 1) && tile_x + TW + 4 > W_);
        int gyc = valid ? gy : 0;
        off2[i] = (c * H_ + gyc) * W_ + tile_x - 4 + q * 4;
        if (q == 0 && tile_x == 0) off2[i] += 4;  // keep ptr in-bounds (unread, sz=0)
        sm2[i]  = ((c * S2R + r) * RW + q * 4) * 4;
        pr2[i]  = valid;
    }

    // packed accumulators: pp=0 -> pixels (0,1), pp=1 -> (2,3)
    uint64_t acc0[DG][9], acc1[DG][9];
#pragma unroll
    for (int d = 0; d < DG; d++)
#pragma unroll
        for (int x = 0; x < 9; x++) { acc0[d][x] = 0ull; acc1[d][x] = 0ull; }

    auto stage = [&](int buf, int cb) {
        const float* f1c = f1n + (size_t)cb * CCH * H_ * W_;
        const float* f2c = f2n + (size_t)cb * CCH * H_ * W_;
        uint32_t d1 = s1b + (uint32_t)buf * (CCH * TH * TW * 4);
        uint32_t d2 = s2b + (uint32_t)buf * (CCH * S2R * RW * 4);
        // f1: 256 f4 / 64 thr = 4 each; 64 f4 per channel (8 rows x 8)
#pragma unroll
        for (int i = 0; i < F1_F4 / THREADS; i++) {
            int idx = tid + THREADS * i;
            int c   = idx >> 6;
            int rem = idx & 63;
            int r   = rem >> 3;
            int q   = rem & 7;
            cp_async16(d1 + (uint32_t)(((c * TH + r) * TW + q * 4) * 4),
                       f1c + ((size_t)c * H_ + tile_y + r) * W_ + tile_x + q * 4,
                       true);
        }
#pragma unroll
        for (int i = 0; i < ND2; i++) {
            if (act2[i])
                cp_async16(d2 + (uint32_t)sm2[i], f2c + off2[i], pr2[i]);
        }
    };

    // ---- pipeline prologue ----
    stage(0, 0); cp_commit();
    stage(1, 1); cp_commit();

    for (int cb = 0; cb < NCHUNK; cb++) {
        cp_wait1();
        __syncthreads();

        const int buf = cb & 1;
#pragma unroll
        for (int c = 0; c < CCH; c++) {
            uint64_t a01, a23;
            {
                float4 av = *reinterpret_cast<const float4*>(&s1[buf][c][ty][tx * 4]);
                a01 = pk2(av.x, av.y);
                a23 = pk2(av.z, av.w);
            }
#pragma unroll
            for (int dyi = 0; dyi < DG; dyi++) {
                const float* row = &s2[buf][c][ty + dyi][tx * 4];
                float4 b0 = *reinterpret_cast<const float4*>(row);
                float4 b1 = *reinterpret_cast<const float4*>(row + 4);
                float4 b2 = *reinterpret_cast<const float4*>(row + 8);
                // even pairs (natural register pairs from the float4 loads)
                uint64_t pe0 = pk2(b0.x, b0.y);
                uint64_t pe1 = pk2(b0.z, b0.w);
                uint64_t pe2 = pk2(b1.x, b1.y);
                uint64_t pe3 = pk2(b1.z, b1.w);
                uint64_t pe4 = pk2(b2.x, b2.y);
                uint64_t pe5 = pk2(b2.z, b2.w);
                // odd pairs (cross-pair packs)
                uint64_t po0 = pk2(b0.y, b0.z);
                uint64_t po1 = pk2(b0.w, b1.x);
                uint64_t po2 = pk2(b1.y, b1.z);
                uint64_t po3 = pk2(b1.w, b2.x);
                uint64_t po4 = pk2(b2.y, b2.z);

                // pair(k) = (r[k], r[k+1]); pp=0 uses pair(dx), pp=1 uses pair(dx+2)
                uint64_t pr[11] = {pe0, po0, pe1, po1, pe2, po2,
                                   pe3, po3, pe4, po4, pe5};
#pragma unroll
                for (int dx = 0; dx < 9; dx++) {
                    fma2(acc0[dyi][dx], a01, pr[dx]);
                    fma2(acc1[dyi][dx], a23, pr[dx + 2]);
                }
            }
        }

        __syncthreads();
        if (cb + 2 < NCHUNK) stage(buf, cb + 2);
        cp_commit();
    }

    // ---- epilogue ----
    const float inv = 1.0f / (float)C_;
    float* outn = out + (size_t)n * 81 * H_ * W_;
    const int y = tile_y + ty;
    const int x = tile_x + tx * 4;
#pragma unroll
    for (int dyi = 0; dyi < DG; dyi++)
#pragma unroll
        for (int dx = 0; dx < 9; dx++) {
            int k = (dy0 + dyi) * 9 + dx;
            float v0, v1, v2, v3;
            upk(acc0[dyi][dx], v0, v1);
            upk(acc1[dyi][dx], v2, v3);
            float4 v = make_float4(v0 * inv, v1 * inv, v2 * inv, v3 * inv);
            *reinterpret_cast<float4*>(outn + ((size_t)k * H_ + y) * W_ + x) = v;
        }
}

extern "C" void kernel_launch(void* const* d_in, const int* in_sizes, int n_in,
                              void* d_out, int out_size)
{
    const float* f1 = (const float*)d_in[0];
    const float* f2 = (const float*)d_in[1];
    float* out = (float*)d_out;

    dim3 block(8, 8);                       // 64 threads
    dim3 grid(W_ / TW, H_ / TH, N_ * 3);    // 7 x 12 x 24 = 2016
    costvol_kernel<<<grid, block>>>(f1, f2, out);
}